// round 1
// baseline (speedup 1.0000x reference)
#include <cuda_runtime.h>
#include <math.h>

// Problem constants (fixed shapes from reference)
#define Bsz 4
#define Tn  2048
#define Cn  1024
#define Hn  8
#define Dn  128
#define Dff 4096
#define Mrows (Bsz*Tn)   // 8192
#define SCALE 11.313708498984761f  // sqrt(128), NOTE: multiply (faithful to reference)

// ---------------- scratch (no allocations allowed) ----------------
__device__ float g_h [(size_t)Mrows*Cn];   // LN1 output
__device__ float g_q [(size_t)Mrows*Cn];   // Q as (B,T,H*D)
__device__ float g_k [(size_t)Mrows*Cn];
__device__ float g_v [(size_t)Mrows*Cn];
__device__ float g_x1[(size_t)Mrows*Cn];   // x + attn_out
__device__ float g_h2[(size_t)Mrows*Cn];   // LN2 output
__device__ float g_ff[(size_t)Mrows*Dff];  // FF hidden

// ---------------- LayerNorm: one block per row, 256 threads, float4 ----------------
__global__ __launch_bounds__(256) void ln_kernel(
    const float* __restrict__ x, const float* __restrict__ g,
    const float* __restrict__ bta, float* __restrict__ out)
{
    long row = blockIdx.x;
    int tid = threadIdx.x;
    const float4* xr = (const float4*)(x + row*(long)Cn);
    float4 v = xr[tid];
    float s = v.x + v.y + v.z + v.w;

    __shared__ float sh[34];
    int lane = tid & 31, wid = tid >> 5;
    #pragma unroll
    for (int o = 16; o > 0; o >>= 1) s += __shfl_xor_sync(0xffffffffu, s, o);
    if (lane == 0) sh[wid] = s;
    __syncthreads();
    if (tid == 0) {
        float t = 0.f;
        #pragma unroll
        for (int w = 0; w < 8; w++) t += sh[w];
        sh[32] = t * (1.0f / Cn);
    }
    __syncthreads();
    float mu = sh[32];
    float dx0 = v.x - mu, dx1 = v.y - mu, dx2 = v.z - mu, dx3 = v.w - mu;
    float ss = dx0*dx0 + dx1*dx1 + dx2*dx2 + dx3*dx3;
    #pragma unroll
    for (int o = 16; o > 0; o >>= 1) ss += __shfl_xor_sync(0xffffffffu, ss, o);
    __syncthreads();
    if (lane == 0) sh[wid] = ss;
    __syncthreads();
    if (tid == 0) {
        float t = 0.f;
        #pragma unroll
        for (int w = 0; w < 8; w++) t += sh[w];
        sh[33] = rsqrtf(t * (1.0f / Cn) + 1e-5f);
    }
    __syncthreads();
    float rstd = sh[33];
    float4 gg = ((const float4*)g)[tid];
    float4 bb = ((const float4*)bta)[tid];
    float4 o4;
    o4.x = dx0 * rstd * gg.x + bb.x;
    o4.y = dx1 * rstd * gg.y + bb.y;
    o4.z = dx2 * rstd * gg.z + bb.z;
    o4.w = dx3 * rstd * gg.w + bb.w;
    ((float4*)(out + row*(long)Cn))[tid] = o4;
}

// ---------------- Generic tiled SGEMM: 128x128 tile, BK=8, 256 thr, 8x8 micro ----------------
// C = A(MxK) * B(KxN) [+bias][relu][+residual], optional batch via blockIdx.z strides.
// Requires M%128==0, N%128==0, K%8==0 (true for all uses here).
__global__ __launch_bounds__(256) void sgemm_kernel(
    const float* __restrict__ A, const float* __restrict__ Bm, float* __restrict__ Cm,
    int M, int N, int K, int lda, int ldb, int ldc,
    long sA, long sB, long sC,
    const float* __restrict__ bias, int applyRelu,
    const float* __restrict__ res, int ldres, long sRes)
{
    __shared__ float As[8][128];
    __shared__ float Bs[8][128];

    int bz = blockIdx.z;
    A  += bz * sA;
    Bm += bz * sB;
    Cm += bz * sC;
    if (res) res += bz * sRes;

    int brow = blockIdx.y * 128;
    int bcol = blockIdx.x * 128;
    int tid = threadIdx.x;
    int ty = tid >> 4, tx = tid & 15;

    float acc[8][8];
    #pragma unroll
    for (int i = 0; i < 8; i++)
        #pragma unroll
        for (int j = 0; j < 8; j++) acc[i][j] = 0.f;

    int arow  = tid >> 1,  ac4 = (tid & 1) * 4;
    int brl   = tid >> 5,  bc4 = (tid & 31) * 4;
    const float* Aptr = A + (long)(brow + arow) * lda + ac4;
    const float* Bptr = Bm + (long)brl * ldb + bcol + bc4;

    for (int k0 = 0; k0 < K; k0 += 8) {
        float4 av = *(const float4*)Aptr; Aptr += 8;
        float4 bv = *(const float4*)Bptr; Bptr += (long)8 * ldb;
        __syncthreads();  // previous iteration's reads complete
        As[ac4 + 0][arow] = av.x;
        As[ac4 + 1][arow] = av.y;
        As[ac4 + 2][arow] = av.z;
        As[ac4 + 3][arow] = av.w;
        *(float4*)(&Bs[brl][bc4]) = bv;
        __syncthreads();
        #pragma unroll
        for (int kk = 0; kk < 8; kk++) {
            float a[8], b[8];
            *(float4*)(a)     = *(const float4*)(&As[kk][ty*8]);
            *(float4*)(a + 4) = *(const float4*)(&As[kk][ty*8 + 4]);
            *(float4*)(b)     = *(const float4*)(&Bs[kk][tx*8]);
            *(float4*)(b + 4) = *(const float4*)(&Bs[kk][tx*8 + 4]);
            #pragma unroll
            for (int i = 0; i < 8; i++)
                #pragma unroll
                for (int j = 0; j < 8; j++)
                    acc[i][j] += a[i] * b[j];
        }
    }

    int crow = brow + ty * 8;
    int ccol = bcol + tx * 8;
    #pragma unroll
    for (int i = 0; i < 8; i++) {
        float outv[8];
        #pragma unroll
        for (int j = 0; j < 8; j++) outv[j] = acc[i][j];
        if (bias) {
            #pragma unroll
            for (int j = 0; j < 8; j++) outv[j] += bias[ccol + j];
        }
        if (applyRelu) {
            #pragma unroll
            for (int j = 0; j < 8; j++) outv[j] = fmaxf(outv[j], 0.f);
        }
        if (res) {
            #pragma unroll
            for (int j = 0; j < 8; j++) outv[j] += res[(long)(crow + i) * ldres + ccol + j];
        }
        float* dst = Cm + (long)(crow + i) * ldc + ccol;
        *(float4*)(dst)     = *(float4*)(outv);
        *(float4*)(dst + 4) = *(float4*)(outv + 4);
    }
}

// ---------------- Flash attention (fp32 online softmax) ----------------
// Q/K/V stored as (B,T,H*D); grid = (T/64, B*H); 256 threads; ~117KB dyn smem.
// Writes x1 = x + attn_out.
#define QT_LD 68   // padded leading dim for Qt/Kt (64 -> 68)
#define S_LD  65
#define ATTN_SMEM_FLOATS (128*QT_LD*2 + 64*128 + 64*S_LD + 64*3)
#define ATTN_SMEM_BYTES  (ATTN_SMEM_FLOATS * 4)

__global__ __launch_bounds__(256) void attn_kernel(
    const float* __restrict__ Q, const float* __restrict__ K, const float* __restrict__ V,
    const float* __restrict__ x, float* __restrict__ x1)
{
    extern __shared__ float sm[];
    float* Qt   = sm;                    // [128][QT_LD] transposed Q tile
    float* Kt   = Qt + 128*QT_LD;        // [128][QT_LD] transposed K tile
    float* Vs   = Kt + 128*QT_LD;        // [64][128]
    float* S    = Vs + 64*128;           // [64][S_LD]
    float* mrow = S + 64*S_LD;           // [64]
    float* lrow = mrow + 64;             // [64]
    float* arow = lrow + 64;             // [64]

    int bh = blockIdx.y;
    int b  = bh / Hn, h = bh % Hn;
    int q0 = blockIdx.x * 64;
    int tid = threadIdx.x;

    const float* Qg = Q + ((long)b*Tn + q0) * Cn + h*Dn;
    const float* Kg = K + (long)b*Tn*Cn + h*Dn;
    const float* Vg = V + (long)b*Tn*Cn + h*Dn;

    // Load Q tile transposed: Qt[d][i]
    #pragma unroll
    for (int it = 0; it < 8; it++) {
        int idx = tid + it*256;
        int r = idx >> 5, c4 = (idx & 31) * 4;
        float4 t = *(const float4*)(Qg + (long)r*Cn + c4);
        Qt[(c4+0)*QT_LD + r] = t.x;
        Qt[(c4+1)*QT_LD + r] = t.y;
        Qt[(c4+2)*QT_LD + r] = t.z;
        Qt[(c4+3)*QT_LD + r] = t.w;
    }
    if (tid < 64) { mrow[tid] = -1e30f; lrow[tid] = 0.f; }

    int ty4 = (tid >> 4) * 4;     // row group (shared between S and O stages)
    int tx4 = (tid & 15) * 4;     // S col group
    int tx8 = (tid & 15) * 8;     // O col group

    float acc[4][8];
    #pragma unroll
    for (int i = 0; i < 4; i++)
        #pragma unroll
        for (int j = 0; j < 8; j++) acc[i][j] = 0.f;

    for (int kt = 0; kt < Tn/64; kt++) {
        __syncthreads();   // prev PV done; safe to overwrite Kt/Vs
        const float* Kgt = Kg + (long)kt*64*Cn;
        const float* Vgt = Vg + (long)kt*64*Cn;
        #pragma unroll
        for (int it = 0; it < 8; it++) {
            int idx = tid + it*256;
            int r = idx >> 5, c4 = (idx & 31) * 4;
            float4 t = *(const float4*)(Kgt + (long)r*Cn + c4);
            Kt[(c4+0)*QT_LD + r] = t.x;
            Kt[(c4+1)*QT_LD + r] = t.y;
            Kt[(c4+2)*QT_LD + r] = t.z;
            Kt[(c4+3)*QT_LD + r] = t.w;
            float4 u = *(const float4*)(Vgt + (long)r*Cn + c4);
            *(float4*)(Vs + r*128 + c4) = u;
        }
        __syncthreads();

        // S[64x64] = Q Kt^T * SCALE
        float s4[4][4];
        #pragma unroll
        for (int i = 0; i < 4; i++)
            #pragma unroll
            for (int j = 0; j < 4; j++) s4[i][j] = 0.f;
        #pragma unroll 4
        for (int d = 0; d < 128; d++) {
            float a[4], bb[4];
            *(float4*)a  = *(const float4*)(&Qt[d*QT_LD + ty4]);
            *(float4*)bb = *(const float4*)(&Kt[d*QT_LD + tx4]);
            #pragma unroll
            for (int i = 0; i < 4; i++)
                #pragma unroll
                for (int j = 0; j < 4; j++)
                    s4[i][j] += a[i] * bb[j];
        }
        #pragma unroll
        for (int i = 0; i < 4; i++)
            #pragma unroll
            for (int j = 0; j < 4; j++)
                S[(ty4 + i)*S_LD + tx4 + j] = s4[i][j] * SCALE;
        __syncthreads();

        // Online softmax per row (threads 0..63)
        if (tid < 64) {
            float* Sr = S + tid*S_LD;
            float mt = -1e30f;
            #pragma unroll 8
            for (int j = 0; j < 64; j++) mt = fmaxf(mt, Sr[j]);
            float mold = mrow[tid];
            float mnew = fmaxf(mold, mt);
            float al = __expf(mold - mnew);
            float sum = 0.f;
            #pragma unroll 8
            for (int j = 0; j < 64; j++) {
                float p = __expf(Sr[j] - mnew);
                Sr[j] = p;
                sum += p;
            }
            lrow[tid] = lrow[tid] * al + sum;
            mrow[tid] = mnew;
            arow[tid] = al;
        }
        __syncthreads();

        // acc = acc*alpha + P @ V
        float al[4];
        #pragma unroll
        for (int i = 0; i < 4; i++) al[i] = arow[ty4 + i];
        #pragma unroll
        for (int i = 0; i < 4; i++)
            #pragma unroll
            for (int j = 0; j < 8; j++) acc[i][j] *= al[i];
        #pragma unroll 4
        for (int jj = 0; jj < 64; jj++) {
            float p[4];
            #pragma unroll
            for (int i = 0; i < 4; i++) p[i] = S[(ty4 + i)*S_LD + jj];
            float vv[8];
            *(float4*)(vv)     = *(const float4*)(&Vs[jj*128 + tx8]);
            *(float4*)(vv + 4) = *(const float4*)(&Vs[jj*128 + tx8 + 4]);
            #pragma unroll
            for (int i = 0; i < 4; i++)
                #pragma unroll
                for (int j = 0; j < 8; j++)
                    acc[i][j] += p[i] * vv[j];
        }
    }

    // epilogue: x1 = x + O/l
    #pragma unroll
    for (int i = 0; i < 4; i++) {
        float invl = 1.0f / lrow[ty4 + i];
        long roff = ((long)b*Tn + q0 + ty4 + i) * Cn + h*Dn + tx8;
        const float* xs = x + roff;
        float* dst = x1 + roff;
        float o[8];
        #pragma unroll
        for (int j = 0; j < 8; j++) o[j] = acc[i][j] * invl + xs[j];
        *(float4*)(dst)     = *(float4*)(o);
        *(float4*)(dst + 4) = *(float4*)(o + 4);
    }
}

// ---------------- host launcher ----------------
extern "C" void kernel_launch(void* const* d_in, const int* in_sizes, int n_in,
                              void* d_out, int out_size)
{
    const float* x     = (const float*)d_in[0];
    const float* wq    = (const float*)d_in[1];
    const float* wk    = (const float*)d_in[2];
    const float* wv    = (const float*)d_in[3];
    const float* w1    = (const float*)d_in[4];
    const float* b1    = (const float*)d_in[5];
    const float* w2    = (const float*)d_in[6];
    const float* b2    = (const float*)d_in[7];
    const float* ln1g  = (const float*)d_in[8];
    const float* ln1b  = (const float*)d_in[9];
    const float* ln2g  = (const float*)d_in[10];
    const float* ln2b  = (const float*)d_in[11];
    float* out = (float*)d_out;

    float *h, *q, *k, *v, *x1, *h2, *ff;
    cudaGetSymbolAddress((void**)&h,  g_h);
    cudaGetSymbolAddress((void**)&q,  g_q);
    cudaGetSymbolAddress((void**)&k,  g_k);
    cudaGetSymbolAddress((void**)&v,  g_v);
    cudaGetSymbolAddress((void**)&x1, g_x1);
    cudaGetSymbolAddress((void**)&h2, g_h2);
    cudaGetSymbolAddress((void**)&ff, g_ff);

    cudaFuncSetAttribute(attn_kernel, cudaFuncAttributeMaxDynamicSharedMemorySize,
                         ATTN_SMEM_BYTES);

    // 1) LN1
    ln_kernel<<<Mrows, 256>>>(x, ln1g, ln1b, h);

    // 2) Q/K/V projections: batched over heads (z), output (B,T,H*D) col slice z*128
    dim3 pg(1, Mrows/128, Hn);
    sgemm_kernel<<<pg, 256>>>(h, wq, q, Mrows, Dn, Cn, Cn, Dn, Cn,
                              0L, (long)Cn*Dn, (long)Dn, nullptr, 0, nullptr, 0, 0L);
    sgemm_kernel<<<pg, 256>>>(h, wk, k, Mrows, Dn, Cn, Cn, Dn, Cn,
                              0L, (long)Cn*Dn, (long)Dn, nullptr, 0, nullptr, 0, 0L);
    sgemm_kernel<<<pg, 256>>>(h, wv, v, Mrows, Dn, Cn, Cn, Dn, Cn,
                              0L, (long)Cn*Dn, (long)Dn, nullptr, 0, nullptr, 0, 0L);

    // 3) attention + residual -> x1
    attn_kernel<<<dim3(Tn/64, Bsz*Hn), 256, ATTN_SMEM_BYTES>>>(q, k, v, x, x1);

    // 4) LN2
    ln_kernel<<<Mrows, 256>>>(x1, ln2g, ln2b, h2);

    // 5) FF1: relu(h2 @ w1 + b1)
    sgemm_kernel<<<dim3(Dff/128, Mrows/128, 1), 256>>>(h2, w1, ff, Mrows, Dff, Cn,
                              Cn, Dff, Dff, 0L, 0L, 0L, b1, 1, nullptr, 0, 0L);

    // 6) FF2: out = x1 + (ff @ w2 + b2)
    sgemm_kernel<<<dim3(Cn/128, Mrows/128, 1), 256>>>(ff, w2, out, Mrows, Cn, Dff,
                              Dff, Cn, Cn, 0L, 0L, 0L, b2, 0, x1, Cn, 0L);
}

// round 3
// speedup vs baseline: 1.5952x; 1.5952x over previous
#include <cuda_runtime.h>
#include <math.h>
#include <stdint.h>

// Problem constants
#define Bsz 4
#define Tn  2048
#define Cn  1024
#define Hn  8
#define Dn  128
#define DffN 4096
#define Mrows (Bsz*Tn)   // 8192
#define SCALE 11.313708498984761f  // sqrt(128), multiply (faithful to reference)

// ---------------- scratch ----------------
__device__ float g_h [(size_t)Mrows*Cn];
__device__ float g_q [(size_t)Mrows*Cn];
__device__ float g_k [(size_t)Mrows*Cn];
__device__ float g_v [(size_t)Mrows*Cn];
__device__ float g_x1[(size_t)Mrows*Cn];
__device__ float g_h2[(size_t)Mrows*Cn];
__device__ float g_ff[(size_t)Mrows*DffN];

// ---------------- helpers ----------------
__device__ __forceinline__ uint32_t cvt_tf32(float x){
    uint32_t u; asm("cvt.rna.tf32.f32 %0, %1;" : "=r"(u) : "f"(x)); return u;
}
__device__ __forceinline__ void mma8(float* d, const uint32_t* a, const uint32_t* b){
    asm volatile("mma.sync.aligned.m16n8k8.row.col.f32.tf32.tf32.f32 "
        "{%0,%1,%2,%3},{%4,%5,%6,%7},{%8,%9},{%0,%1,%2,%3};"
        : "+f"(d[0]),"+f"(d[1]),"+f"(d[2]),"+f"(d[3])
        : "r"(a[0]),"r"(a[1]),"r"(a[2]),"r"(a[3]),"r"(b[0]),"r"(b[1]));
}

// ---------------- LayerNorm (unchanged, memory-bound) ----------------
__global__ __launch_bounds__(256) void ln_kernel(
    const float* __restrict__ x, const float* __restrict__ g,
    const float* __restrict__ bta, float* __restrict__ out)
{
    long row = blockIdx.x;
    int tid = threadIdx.x;
    const float4* xr = (const float4*)(x + row*(long)Cn);
    float4 v = xr[tid];
    float s = v.x + v.y + v.z + v.w;

    __shared__ float sh[34];
    int lane = tid & 31, wid = tid >> 5;
    #pragma unroll
    for (int o = 16; o > 0; o >>= 1) s += __shfl_xor_sync(0xffffffffu, s, o);
    if (lane == 0) sh[wid] = s;
    __syncthreads();
    if (tid == 0) {
        float t = 0.f;
        #pragma unroll
        for (int w = 0; w < 8; w++) t += sh[w];
        sh[32] = t * (1.0f / Cn);
    }
    __syncthreads();
    float mu = sh[32];
    float dx0 = v.x - mu, dx1 = v.y - mu, dx2 = v.z - mu, dx3 = v.w - mu;
    float ss = dx0*dx0 + dx1*dx1 + dx2*dx2 + dx3*dx3;
    #pragma unroll
    for (int o = 16; o > 0; o >>= 1) ss += __shfl_xor_sync(0xffffffffu, ss, o);
    __syncthreads();
    if (lane == 0) sh[wid] = ss;
    __syncthreads();
    if (tid == 0) {
        float t = 0.f;
        #pragma unroll
        for (int w = 0; w < 8; w++) t += sh[w];
        sh[33] = rsqrtf(t * (1.0f / Cn) + 1e-5f);
    }
    __syncthreads();
    float rstd = sh[33];
    float4 gg = ((const float4*)g)[tid];
    float4 bb = ((const float4*)bta)[tid];
    float4 o4;
    o4.x = dx0 * rstd * gg.x + bb.x;
    o4.y = dx1 * rstd * gg.y + bb.y;
    o4.z = dx2 * rstd * gg.z + bb.z;
    o4.w = dx3 * rstd * gg.w + bb.w;
    ((float4*)(out + row*(long)Cn))[tid] = o4;
}

// ---------------- TF32 MMA GEMM: 128x128 block, BK=16, 256 thr ----------------
// warps: 2(m) x 4(n) -> warp tile 64x32. SPLIT=3 -> 3xTF32 precision.
template<int SPLIT>
__global__ __launch_bounds__(256) void mma_gemm(
    const float* __restrict__ A, const float* __restrict__ Bm, float* __restrict__ Cm,
    int M, int N, int K, int lda, int ldb, int ldc,
    long sB, long sC,
    const float* __restrict__ bias, int applyRelu,
    const float* __restrict__ res, int ldres)
{
    constexpr int ST = 136;
    constexpr int TILE = 16*ST;
    __shared__ uint32_t smem[(SPLIT==3?4:2)*TILE];
    uint32_t* Ah = smem;
    uint32_t* Bh = smem + TILE;
    uint32_t* Al = (SPLIT==3) ? smem + 2*TILE : smem;
    uint32_t* Bl = (SPLIT==3) ? smem + 3*TILE : smem;

    int bz = blockIdx.z;
    Bm += bz * sB;
    Cm += bz * sC;

    int brow = blockIdx.y*128, bcol = blockIdx.x*128;
    int tid = threadIdx.x, lane = tid&31, wid = tid>>5;
    int wm = wid>>2, wn = wid&3;

    float acc[4][4][4];
    #pragma unroll
    for (int i=0;i<4;i++)
        #pragma unroll
        for (int j=0;j<4;j++)
            #pragma unroll
            for (int t=0;t<4;t++) acc[i][j][t]=0.f;

    int a_r0 = tid>>2;
    int a_k0 = (tid&3)*4;
    const float* Ap = A + (long)(brow + a_r0)*lda + a_k0;
    int b_k0 = tid>>5;
    int b_c0 = lane*4;
    const float* Bp = Bm + (long)b_k0*ldb + bcol + b_c0;

    for (int k0 = 0; k0 < K; k0 += 16) {
        float4 av0 = *(const float4*)(Ap);
        float4 av1 = *(const float4*)(Ap + (long)64*lda);
        float4 bv0 = *(const float4*)(Bp);
        float4 bv1 = *(const float4*)(Bp + (long)8*ldb);
        Ap += 16; Bp += (long)16*ldb;
        __syncthreads();
        {
            float va[4] = {av0.x,av0.y,av0.z,av0.w};
            float vb[4] = {av1.x,av1.y,av1.z,av1.w};
            #pragma unroll
            for (int j=0;j<4;j++){
                uint32_t h0 = cvt_tf32(va[j]);
                Ah[(a_k0+j)*ST + a_r0] = h0;
                if (SPLIT==3) Al[(a_k0+j)*ST + a_r0] = cvt_tf32(va[j]-__uint_as_float(h0));
                uint32_t h1 = cvt_tf32(vb[j]);
                Ah[(a_k0+j)*ST + a_r0 + 64] = h1;
                if (SPLIT==3) Al[(a_k0+j)*ST + a_r0 + 64] = cvt_tf32(vb[j]-__uint_as_float(h1));
            }
            uint4 u0, u1;
            u0.x=cvt_tf32(bv0.x); u0.y=cvt_tf32(bv0.y); u0.z=cvt_tf32(bv0.z); u0.w=cvt_tf32(bv0.w);
            u1.x=cvt_tf32(bv1.x); u1.y=cvt_tf32(bv1.y); u1.z=cvt_tf32(bv1.z); u1.w=cvt_tf32(bv1.w);
            *(uint4*)(&Bh[b_k0*ST + b_c0])     = u0;
            *(uint4*)(&Bh[(b_k0+8)*ST + b_c0]) = u1;
            if (SPLIT==3){
                uint4 l0, l1;
                l0.x=cvt_tf32(bv0.x-__uint_as_float(u0.x)); l0.y=cvt_tf32(bv0.y-__uint_as_float(u0.y));
                l0.z=cvt_tf32(bv0.z-__uint_as_float(u0.z)); l0.w=cvt_tf32(bv0.w-__uint_as_float(u0.w));
                l1.x=cvt_tf32(bv1.x-__uint_as_float(u1.x)); l1.y=cvt_tf32(bv1.y-__uint_as_float(u1.y));
                l1.z=cvt_tf32(bv1.z-__uint_as_float(u1.z)); l1.w=cvt_tf32(bv1.w-__uint_as_float(u1.w));
                *(uint4*)(&Bl[b_k0*ST + b_c0])     = l0;
                *(uint4*)(&Bl[(b_k0+8)*ST + b_c0]) = l1;
            }
        }
        __syncthreads();

        #pragma unroll
        for (int ks = 0; ks < 16; ks += 8) {
            int kk = ks + (lane&3);
            uint32_t bhf[4][2], blf[4][2];
            #pragma unroll
            for (int nt=0;nt<4;nt++){
                int c = wn*32 + nt*8 + (lane>>2);
                bhf[nt][0] = Bh[kk*ST + c];
                bhf[nt][1] = Bh[(kk+4)*ST + c];
                if (SPLIT==3){
                    blf[nt][0] = Bl[kk*ST + c];
                    blf[nt][1] = Bl[(kk+4)*ST + c];
                }
            }
            #pragma unroll
            for (int mt=0;mt<4;mt++){
                int m = wm*64 + mt*16 + (lane>>2);
                uint32_t ah[4], alr[4];
                ah[0]=Ah[kk*ST+m];     ah[1]=Ah[kk*ST+m+8];
                ah[2]=Ah[(kk+4)*ST+m]; ah[3]=Ah[(kk+4)*ST+m+8];
                if (SPLIT==3){
                    alr[0]=Al[kk*ST+m];     alr[1]=Al[kk*ST+m+8];
                    alr[2]=Al[(kk+4)*ST+m]; alr[3]=Al[(kk+4)*ST+m+8];
                }
                #pragma unroll
                for (int nt=0;nt<4;nt++){
                    mma8(acc[mt][nt], ah, bhf[nt]);
                    if (SPLIT==3){
                        mma8(acc[mt][nt], ah, blf[nt]);
                        mma8(acc[mt][nt], alr, bhf[nt]);
                    }
                }
            }
        }
    }

    // epilogue
    #pragma unroll
    for (int mt=0;mt<4;mt++){
        int r0 = brow + wm*64 + mt*16 + (lane>>2);
        #pragma unroll
        for (int nt=0;nt<4;nt++){
            int c = bcol + wn*32 + nt*8 + (lane&3)*2;
            float2 v0 = make_float2(acc[mt][nt][0], acc[mt][nt][1]);
            float2 v1 = make_float2(acc[mt][nt][2], acc[mt][nt][3]);
            if (bias){
                float b0=bias[c], b1=bias[c+1];
                v0.x+=b0; v0.y+=b1; v1.x+=b0; v1.y+=b1;
            }
            if (applyRelu){
                v0.x=fmaxf(v0.x,0.f); v0.y=fmaxf(v0.y,0.f);
                v1.x=fmaxf(v1.x,0.f); v1.y=fmaxf(v1.y,0.f);
            }
            if (res){
                v0.x += res[(long)r0*ldres + c];     v0.y += res[(long)r0*ldres + c+1];
                v1.x += res[(long)(r0+8)*ldres + c]; v1.y += res[(long)(r0+8)*ldres + c+1];
            }
            *(float2*)(Cm + (long)r0*ldc + c)     = v0;
            *(float2*)(Cm + (long)(r0+8)*ldc + c) = v1;
        }
    }
}

// ---------------- Flash attention with TF32 MMA ----------------
// Q tile 64 rows/CTA; QK^T in 3xTF32 (score chain), PV in 1xTF32.
#define QS 132
#define VSd 136
#define SSd 68
#define ATTN_WORDS (4*64*QS + 64*VSd + 64*SSd + 3*64 + 8*64)
#define ATTN_BYTES (ATTN_WORDS*4)

__global__ __launch_bounds__(256) void attn_mma(
    const float* __restrict__ Q, const float* __restrict__ K, const float* __restrict__ V,
    const float* __restrict__ x, float* __restrict__ x1)
{
    extern __shared__ uint32_t sm[];
    uint32_t* Qh = sm;
    uint32_t* Ql = Qh + 64*QS;
    uint32_t* Kh = Ql + 64*QS;
    uint32_t* Kl = Kh + 64*QS;
    uint32_t* Vt = Kl + 64*QS;
    float* Ssm  = (float*)(Vt + 64*VSd);
    float* mrow = Ssm + 64*SSd;
    float* lrow = mrow + 64;
    float* arow = lrow + 64;
    float* pmax = arow + 64;
    float* psum = pmax + 4*64;

    int bh = blockIdx.y; int b = bh>>3, h = bh&7;
    int q0 = blockIdx.x*64;
    int tid = threadIdx.x, lane = tid&31, wid = tid>>5;
    int wm = wid>>1, wn = wid&1;   // 4(m) x 2(n)

    const float* Qg = Q + ((long)b*Tn + q0)*Cn + h*Dn;
    const float* Kg = K + (long)b*Tn*Cn + h*Dn;
    const float* Vg = V + (long)b*Tn*Cn + h*Dn;

    // Load + split Q tile (once)
    #pragma unroll
    for (int it=0; it<8; it++){
        int idx = tid + it*256;
        int r = idx>>5, c = (idx&31)*4;
        float4 t = *(const float4*)(Qg + (long)r*Cn + c);
        float v[4] = {t.x,t.y,t.z,t.w};
        #pragma unroll
        for (int j=0;j<4;j++){
            uint32_t hh = cvt_tf32(v[j]);
            Qh[r*QS + c + j] = hh;
            Ql[r*QS + c + j] = cvt_tf32(v[j]-__uint_as_float(hh));
        }
    }
    if (tid < 64){ mrow[tid] = -1e30f; lrow[tid] = 0.f; }

    float accO[8][4];
    #pragma unroll
    for (int i=0;i<8;i++)
        #pragma unroll
        for (int j=0;j<4;j++) accO[i][j]=0.f;

    for (int kt = 0; kt < Tn/64; kt++) {
        __syncthreads();  // previous PV / softmax reads done
        const float* Kgt = Kg + (long)kt*64*Cn;
        const float* Vgt = Vg + (long)kt*64*Cn;
        #pragma unroll
        for (int it=0; it<8; it++){
            int idx = tid + it*256;
            int r = idx>>5, c = (idx&31)*4;
            float4 t = *(const float4*)(Kgt + (long)r*Cn + c);
            float v[4] = {t.x,t.y,t.z,t.w};
            #pragma unroll
            for (int j=0;j<4;j++){
                uint32_t hh = cvt_tf32(v[j]);
                Kh[r*QS + c + j] = hh;
                Kl[r*QS + c + j] = cvt_tf32(v[j]-__uint_as_float(hh));
            }
            float4 u = *(const float4*)(Vgt + (long)r*Cn + c);
            uint4 uv;
            uv.x=cvt_tf32(u.x); uv.y=cvt_tf32(u.y); uv.z=cvt_tf32(u.z); uv.w=cvt_tf32(u.w);
            *(uint4*)(&Vt[r*VSd + c]) = uv;
        }
        __syncthreads();

        // S = Q K^T (3xTF32), warp tile 16x32
        float accS[4][4];
        #pragma unroll
        for (int i=0;i<4;i++)
            #pragma unroll
            for (int j=0;j<4;j++) accS[i][j]=0.f;

        #pragma unroll
        for (int ks=0; ks<128; ks+=8){
            int kk = ks + (lane&3);
            uint32_t bhf[4][2], blf[4][2];
            #pragma unroll
            for (int nt=0;nt<4;nt++){
                int c = wn*32 + nt*8 + (lane>>2);
                bhf[nt][0] = Kh[c*QS + kk];
                bhf[nt][1] = Kh[c*QS + kk + 4];
                blf[nt][0] = Kl[c*QS + kk];
                blf[nt][1] = Kl[c*QS + kk + 4];
            }
            int r = wm*16 + (lane>>2);
            uint32_t ah[4], al[4];
            ah[0]=Qh[r*QS+kk];     ah[1]=Qh[(r+8)*QS+kk];
            ah[2]=Qh[r*QS+kk+4];   ah[3]=Qh[(r+8)*QS+kk+4];
            al[0]=Ql[r*QS+kk];     al[1]=Ql[(r+8)*QS+kk];
            al[2]=Ql[r*QS+kk+4];   al[3]=Ql[(r+8)*QS+kk+4];
            #pragma unroll
            for (int nt=0;nt<4;nt++){
                mma8(accS[nt], ah, bhf[nt]);
                mma8(accS[nt], ah, blf[nt]);
                mma8(accS[nt], al, bhf[nt]);
            }
        }
        {
            int r = wm*16 + (lane>>2);
            #pragma unroll
            for (int nt=0;nt<4;nt++){
                int c = wn*32 + nt*8 + (lane&3)*2;
                Ssm[r*SSd + c]       = accS[nt][0]*SCALE;
                Ssm[r*SSd + c + 1]   = accS[nt][1]*SCALE;
                Ssm[(r+8)*SSd + c]   = accS[nt][2]*SCALE;
                Ssm[(r+8)*SSd + c+1] = accS[nt][3]*SCALE;
            }
        }
        __syncthreads();

        // softmax: 4 threads per row
        {
            int r = tid & 63, qd = tid >> 6;
            float* Sr = Ssm + r*SSd + qd*16;
            float mt_ = -1e30f;
            #pragma unroll
            for (int j=0;j<16;j++) mt_ = fmaxf(mt_, Sr[j]);
            pmax[qd*64 + r] = mt_;
            __syncthreads();
            float mold = mrow[r];
            float mnew = fmaxf(mold,
                         fmaxf(fmaxf(pmax[r], pmax[64+r]), fmaxf(pmax[128+r], pmax[192+r])));
            float s_ = 0.f;
            #pragma unroll
            for (int j=0;j<16;j++){
                float p = __expf(Sr[j] - mnew);
                Sr[j] = p; s_ += p;
            }
            psum[qd*64 + r] = s_;
            __syncthreads();
            if (qd == 0){
                float al_ = __expf(mold - mnew);
                lrow[r] = lrow[r]*al_ + psum[r] + psum[64+r] + psum[128+r] + psum[192+r];
                mrow[r] = mnew;
                arow[r] = al_;
            }
        }
        __syncthreads();

        // rescale + PV (1xTF32), warp tile 16x64
        {
            float a0 = arow[wm*16 + (lane>>2)];
            float a1 = arow[wm*16 + (lane>>2) + 8];
            #pragma unroll
            for (int nt=0;nt<8;nt++){
                accO[nt][0]*=a0; accO[nt][1]*=a0;
                accO[nt][2]*=a1; accO[nt][3]*=a1;
            }
            #pragma unroll
            for (int s0=0; s0<64; s0+=8){
                int kk = s0 + (lane&3);
                int r = wm*16 + (lane>>2);
                uint32_t ap[4];
                ap[0]=cvt_tf32(Ssm[r*SSd + kk]);
                ap[1]=cvt_tf32(Ssm[(r+8)*SSd + kk]);
                ap[2]=cvt_tf32(Ssm[r*SSd + kk + 4]);
                ap[3]=cvt_tf32(Ssm[(r+8)*SSd + kk + 4]);
                #pragma unroll
                for (int nt=0;nt<8;nt++){
                    int c = wn*64 + nt*8 + (lane>>2);
                    uint32_t bp[2] = { Vt[kk*VSd + c], Vt[(kk+4)*VSd + c] };
                    mma8(accO[nt], ap, bp);
                }
            }
        }
    }

    __syncthreads();
    // epilogue: x1 = x + O/l
    {
        int r = wm*16 + (lane>>2);
        float i0 = 1.f/lrow[r], i1 = 1.f/lrow[r+8];
        long row0 = (long)b*Tn + q0 + r;
        #pragma unroll
        for (int nt=0;nt<8;nt++){
            int c = h*Dn + wn*64 + nt*8 + (lane&3)*2;
            long o0 = row0*Cn + c, o1 = (row0+8)*Cn + c;
            float2 v0 = make_float2(accO[nt][0]*i0 + x[o0], accO[nt][1]*i0 + x[o0+1]);
            float2 v1 = make_float2(accO[nt][2]*i1 + x[o1], accO[nt][3]*i1 + x[o1+1]);
            *(float2*)(x1 + o0) = v0;
            *(float2*)(x1 + o1) = v1;
        }
    }
}

// ---------------- host launcher ----------------
extern "C" void kernel_launch(void* const* d_in, const int* in_sizes, int n_in,
                              void* d_out, int out_size)
{
    const float* x    = (const float*)d_in[0];
    const float* wq   = (const float*)d_in[1];
    const float* wk   = (const float*)d_in[2];
    const float* wv   = (const float*)d_in[3];
    const float* w1   = (const float*)d_in[4];
    const float* b1   = (const float*)d_in[5];
    const float* w2   = (const float*)d_in[6];
    const float* b2   = (const float*)d_in[7];
    const float* ln1g = (const float*)d_in[8];
    const float* ln1b = (const float*)d_in[9];
    const float* ln2g = (const float*)d_in[10];
    const float* ln2b = (const float*)d_in[11];
    float* out = (float*)d_out;

    float *h, *q, *k, *v, *x1, *h2, *ff;
    cudaGetSymbolAddress((void**)&h,  g_h);
    cudaGetSymbolAddress((void**)&q,  g_q);
    cudaGetSymbolAddress((void**)&k,  g_k);
    cudaGetSymbolAddress((void**)&v,  g_v);
    cudaGetSymbolAddress((void**)&x1, g_x1);
    cudaGetSymbolAddress((void**)&h2, g_h2);
    cudaGetSymbolAddress((void**)&ff, g_ff);

    cudaFuncSetAttribute(attn_mma, cudaFuncAttributeMaxDynamicSharedMemorySize,
                         ATTN_BYTES);

    // 1) LN1
    ln_kernel<<<Mrows, 256>>>(x, ln1g, ln1b, h);

    // 2) projections: q,k in 3xTF32 (score chain), v in 1xTF32
    dim3 pg(1, Mrows/128, Hn);
    mma_gemm<3><<<pg, 256>>>(h, wq, q, Mrows, Dn, Cn, Cn, Dn, Cn,
                             (long)Cn*Dn, (long)Dn, nullptr, 0, nullptr, 0);
    mma_gemm<3><<<pg, 256>>>(h, wk, k, Mrows, Dn, Cn, Cn, Dn, Cn,
                             (long)Cn*Dn, (long)Dn, nullptr, 0, nullptr, 0);
    mma_gemm<1><<<pg, 256>>>(h, wv, v, Mrows, Dn, Cn, Cn, Dn, Cn,
                             (long)Cn*Dn, (long)Dn, nullptr, 0, nullptr, 0);

    // 3) attention + residual
    attn_mma<<<dim3(Tn/64, Bsz*Hn), 256, ATTN_BYTES>>>(q, k, v, x, x1);

    // 4) LN2
    ln_kernel<<<Mrows, 256>>>(x1, ln2g, ln2b, h2);

    // 5) FF1: relu(h2 @ w1 + b1)
    mma_gemm<1><<<dim3(DffN/128, Mrows/128, 1), 256>>>(h2, w1, ff, Mrows, DffN, Cn,
                             Cn, DffN, DffN, 0L, 0L, b1, 1, nullptr, 0);

    // 6) FF2: out = x1 + (ff @ w2 + b2)
    mma_gemm<1><<<dim3(Cn/128, Mrows/128, 1), 256>>>(ff, w2, out, Mrows, Cn, DffN,
                             DffN, Cn, Cn, 0L, 0L, b2, 0, x1, Cn);
}

// round 6
// speedup vs baseline: 2.5795x; 1.6170x over previous
#include <cuda_runtime.h>
#include <math.h>
#include <stdint.h>

// Problem constants
#define Bsz 4
#define Tn  2048
#define Cn  1024
#define Hn  8
#define Dn  128
#define DffN 4096
#define Mrows (Bsz*Tn)   // 8192
#define SCALE 11.313708498984761f  // sqrt(128), multiply (faithful to reference)

// ---------------- scratch ----------------
__device__ float g_h [(size_t)Mrows*Cn];
__device__ float g_q [(size_t)Mrows*Cn];
__device__ float g_k [(size_t)Mrows*Cn];
__device__ float g_v [(size_t)Mrows*Cn];
__device__ float g_x1[(size_t)Mrows*Cn];
__device__ float g_h2[(size_t)Mrows*Cn];
__device__ float g_ff[(size_t)Mrows*DffN];

// ---------------- helpers ----------------
__device__ __forceinline__ uint32_t cvt_tf32(float x){
    uint32_t u; asm("cvt.rna.tf32.f32 %0, %1;" : "=r"(u) : "f"(x)); return u;
}
__device__ __forceinline__ void mma8(float* d, const uint32_t* a, const uint32_t* b){
    asm volatile("mma.sync.aligned.m16n8k8.row.col.f32.tf32.tf32.f32 "
        "{%0,%1,%2,%3},{%4,%5,%6,%7},{%8,%9},{%0,%1,%2,%3};"
        : "+f"(d[0]),"+f"(d[1]),"+f"(d[2]),"+f"(d[3])
        : "r"(a[0]),"r"(a[1]),"r"(a[2]),"r"(a[3]),"r"(b[0]),"r"(b[1]));
}

// ---------------- LayerNorm ----------------
__global__ __launch_bounds__(256) void ln_kernel(
    const float* __restrict__ x, const float* __restrict__ g,
    const float* __restrict__ bta, float* __restrict__ out)
{
    long row = blockIdx.x;
    int tid = threadIdx.x;
    const float4* xr = (const float4*)(x + row*(long)Cn);
    float4 v = xr[tid];
    float s = v.x + v.y + v.z + v.w;

    __shared__ float sh[34];
    int lane = tid & 31, wid = tid >> 5;
    #pragma unroll
    for (int o = 16; o > 0; o >>= 1) s += __shfl_xor_sync(0xffffffffu, s, o);
    if (lane == 0) sh[wid] = s;
    __syncthreads();
    if (tid == 0) {
        float t = 0.f;
        #pragma unroll
        for (int w = 0; w < 8; w++) t += sh[w];
        sh[32] = t * (1.0f / Cn);
    }
    __syncthreads();
    float mu = sh[32];
    float dx0 = v.x - mu, dx1 = v.y - mu, dx2 = v.z - mu, dx3 = v.w - mu;
    float ss = dx0*dx0 + dx1*dx1 + dx2*dx2 + dx3*dx3;
    #pragma unroll
    for (int o = 16; o > 0; o >>= 1) ss += __shfl_xor_sync(0xffffffffu, ss, o);
    __syncthreads();
    if (lane == 0) sh[wid] = ss;
    __syncthreads();
    if (tid == 0) {
        float t = 0.f;
        #pragma unroll
        for (int w = 0; w < 8; w++) t += sh[w];
        sh[33] = rsqrtf(t * (1.0f / Cn) + 1e-5f);
    }
    __syncthreads();
    float rstd = sh[33];
    float4 gg = ((const float4*)g)[tid];
    float4 bb = ((const float4*)bta)[tid];
    float4 o4;
    o4.x = dx0 * rstd * gg.x + bb.x;
    o4.y = dx1 * rstd * gg.y + bb.y;
    o4.z = dx2 * rstd * gg.z + bb.z;
    o4.w = dx3 * rstd * gg.w + bb.w;
    ((float4*)(out + row*(long)Cn))[tid] = o4;
}

// ---------------- TF32 MMA GEMM: 128x128 block, BK=16, 256 thr ----------------
// Ping-pong double-buffered smem; one __syncthreads per K-iter; global loads
// for tile i+1 issued before compute of tile i. SPLIT=3 -> 3xTF32 precision.
template<int SPLIT>
__global__ __launch_bounds__(256) void mma_gemm(
    const float* __restrict__ A, const float* __restrict__ Bm, float* __restrict__ Cm,
    int M, int N, int K, int lda, int ldb, int ldc,
    long sB, long sC,
    const float* __restrict__ bias, int applyRelu,
    const float* __restrict__ res, int ldres)
{
    constexpr int ST = 136;
    constexpr int TILE = 16*ST;
    constexpr int NT = (SPLIT==3) ? 4 : 2;   // tiles per buffer
    extern __shared__ uint32_t smem[];       // 2 * NT * TILE words

    int bz = blockIdx.z;
    Bm += bz * sB;
    Cm += bz * sC;

    int brow = blockIdx.y*128, bcol = blockIdx.x*128;
    int tid = threadIdx.x, lane = tid&31, wid = tid>>5;
    int wm = wid>>2, wn = wid&3;

    float acc[4][4][4];
    #pragma unroll
    for (int i=0;i<4;i++)
        #pragma unroll
        for (int j=0;j<4;j++)
            #pragma unroll
            for (int t=0;t<4;t++) acc[i][j][t]=0.f;

    int a_r0 = tid>>2;
    int a_k0 = (tid&3)*4;
    const float* Ap = A + (long)(brow + a_r0)*lda + a_k0;
    int b_k0 = tid>>5;
    int b_c0 = lane*4;
    const float* Bp = Bm + (long)b_k0*ldb + bcol + b_c0;

    float4 av0, av1, bv0, bv1;

    auto gload = [&](){
        av0 = *(const float4*)(Ap);
        av1 = *(const float4*)(Ap + (long)64*lda);
        bv0 = *(const float4*)(Bp);
        bv1 = *(const float4*)(Bp + (long)8*ldb);
        Ap += 16; Bp += (long)16*ldb;
    };

    auto store_tile = [&](uint32_t* base){
        uint32_t* Ah = base;
        uint32_t* Bh = base + TILE;
        uint32_t* Al = base + 2*TILE;
        uint32_t* Bl = base + 3*TILE;
        float va[4] = {av0.x,av0.y,av0.z,av0.w};
        float vb[4] = {av1.x,av1.y,av1.z,av1.w};
        #pragma unroll
        for (int j=0;j<4;j++){
            uint32_t h0 = cvt_tf32(va[j]);
            Ah[(a_k0+j)*ST + a_r0] = h0;
            if (SPLIT==3) Al[(a_k0+j)*ST + a_r0] = cvt_tf32(va[j]-__uint_as_float(h0));
            uint32_t h1 = cvt_tf32(vb[j]);
            Ah[(a_k0+j)*ST + a_r0 + 64] = h1;
            if (SPLIT==3) Al[(a_k0+j)*ST + a_r0 + 64] = cvt_tf32(vb[j]-__uint_as_float(h1));
        }
        uint4 u0, u1;
        u0.x=cvt_tf32(bv0.x); u0.y=cvt_tf32(bv0.y); u0.z=cvt_tf32(bv0.z); u0.w=cvt_tf32(bv0.w);
        u1.x=cvt_tf32(bv1.x); u1.y=cvt_tf32(bv1.y); u1.z=cvt_tf32(bv1.z); u1.w=cvt_tf32(bv1.w);
        *(uint4*)(&Bh[b_k0*ST + b_c0])     = u0;
        *(uint4*)(&Bh[(b_k0+8)*ST + b_c0]) = u1;
        if (SPLIT==3){
            uint4 l0, l1;
            l0.x=cvt_tf32(bv0.x-__uint_as_float(u0.x)); l0.y=cvt_tf32(bv0.y-__uint_as_float(u0.y));
            l0.z=cvt_tf32(bv0.z-__uint_as_float(u0.z)); l0.w=cvt_tf32(bv0.w-__uint_as_float(u0.w));
            l1.x=cvt_tf32(bv1.x-__uint_as_float(u1.x)); l1.y=cvt_tf32(bv1.y-__uint_as_float(u1.y));
            l1.z=cvt_tf32(bv1.z-__uint_as_float(u1.z)); l1.w=cvt_tf32(bv1.w-__uint_as_float(u1.w));
            *(uint4*)(&Bl[b_k0*ST + b_c0])     = l0;
            *(uint4*)(&Bl[(b_k0+8)*ST + b_c0]) = l1;
        }
    };

    auto compute_tile = [&](const uint32_t* base){
        const uint32_t* Ah = base;
        const uint32_t* Bh = base + TILE;
        const uint32_t* Al = base + 2*TILE;
        const uint32_t* Bl = base + 3*TILE;
        #pragma unroll
        for (int ks = 0; ks < 16; ks += 8) {
            int kk = ks + (lane&3);
            uint32_t bhf[4][2], blf[4][2];
            #pragma unroll
            for (int nt=0;nt<4;nt++){
                int c = wn*32 + nt*8 + (lane>>2);
                bhf[nt][0] = Bh[kk*ST + c];
                bhf[nt][1] = Bh[(kk+4)*ST + c];
                if (SPLIT==3){
                    blf[nt][0] = Bl[kk*ST + c];
                    blf[nt][1] = Bl[(kk+4)*ST + c];
                }
            }
            #pragma unroll
            for (int mt=0;mt<4;mt++){
                int m = wm*64 + mt*16 + (lane>>2);
                uint32_t ah[4], alr[4];
                ah[0]=Ah[kk*ST+m];     ah[1]=Ah[kk*ST+m+8];
                ah[2]=Ah[(kk+4)*ST+m]; ah[3]=Ah[(kk+4)*ST+m+8];
                if (SPLIT==3){
                    alr[0]=Al[kk*ST+m];     alr[1]=Al[kk*ST+m+8];
                    alr[2]=Al[(kk+4)*ST+m]; alr[3]=Al[(kk+4)*ST+m+8];
                }
                #pragma unroll
                for (int nt=0;nt<4;nt++){
                    mma8(acc[mt][nt], ah, bhf[nt]);
                    if (SPLIT==3){
                        mma8(acc[mt][nt], ah, blf[nt]);
                        mma8(acc[mt][nt], alr, bhf[nt]);
                    }
                }
            }
        }
    };

    // prologue: tile 0 -> buffer 0
    gload();
    store_tile(smem);
    __syncthreads();

    int nIter = K >> 4;
    for (int i = 0; i < nIter; i++) {
        uint32_t* cur = smem + (size_t)(i & 1) * (NT*TILE);
        uint32_t* nxt = smem + (size_t)((i & 1) ^ 1) * (NT*TILE);
        bool hasNext = (i + 1 < nIter);
        if (hasNext) gload();          // issue early; latency hides behind compute
        compute_tile(cur);
        if (hasNext) store_tile(nxt);  // other buffer; protected by prev sync
        __syncthreads();
    }

    // epilogue
    #pragma unroll
    for (int mt=0;mt<4;mt++){
        int r0 = brow + wm*64 + mt*16 + (lane>>2);
        #pragma unroll
        for (int nt=0;nt<4;nt++){
            int c = bcol + wn*32 + nt*8 + (lane&3)*2;
            float2 v0 = make_float2(acc[mt][nt][0], acc[mt][nt][1]);
            float2 v1 = make_float2(acc[mt][nt][2], acc[mt][nt][3]);
            if (bias){
                float b0=bias[c], b1=bias[c+1];
                v0.x+=b0; v0.y+=b1; v1.x+=b0; v1.y+=b1;
            }
            if (applyRelu){
                v0.x=fmaxf(v0.x,0.f); v0.y=fmaxf(v0.y,0.f);
                v1.x=fmaxf(v1.x,0.f); v1.y=fmaxf(v1.y,0.f);
            }
            if (res){
                v0.x += res[(long)r0*ldres + c];     v0.y += res[(long)r0*ldres + c+1];
                v1.x += res[(long)(r0+8)*ldres + c]; v1.y += res[(long)(r0+8)*ldres + c+1];
            }
            *(float2*)(Cm + (long)r0*ldc + c)     = v0;
            *(float2*)(Cm + (long)(r0+8)*ldc + c) = v1;
        }
    }
}

// ---------------- Flash attention with TF32 MMA ----------------
// Q tile 64 rows/CTA; QK^T in 3xTF32 (score chain), PV in 1xTF32.
// K/V tiles for iteration kt+1 prefetched into registers during iteration kt.
#define QS 132
#define VSd 136
#define SSd 68
#define ATTN_WORDS (4*64*QS + 64*VSd + 64*SSd + 3*64 + 8*64)
#define ATTN_BYTES (ATTN_WORDS*4)

__global__ __launch_bounds__(256) void attn_mma(
    const float* __restrict__ Q, const float* __restrict__ K, const float* __restrict__ V,
    const float* __restrict__ x, float* __restrict__ x1)
{
    extern __shared__ uint32_t sm[];
    uint32_t* Qh = sm;
    uint32_t* Ql = Qh + 64*QS;
    uint32_t* Kh = Ql + 64*QS;
    uint32_t* Kl = Kh + 64*QS;
    uint32_t* Vt = Kl + 64*QS;
    float* Ssm  = (float*)(Vt + 64*VSd);
    float* mrow = Ssm + 64*SSd;
    float* lrow = mrow + 64;
    float* arow = lrow + 64;
    float* pmax = arow + 64;
    float* psum = pmax + 4*64;

    int bh = blockIdx.y; int b = bh>>3, h = bh&7;
    int q0 = blockIdx.x*64;
    int tid = threadIdx.x, lane = tid&31, wid = tid>>5;
    int wm = wid>>1, wn = wid&1;   // 4(m) x 2(n)

    const float* Qg = Q + ((long)b*Tn + q0)*Cn + h*Dn;
    const float* Kg = K + (long)b*Tn*Cn + h*Dn;
    const float* Vg = V + (long)b*Tn*Cn + h*Dn;

    // Load + split Q tile (once)
    #pragma unroll
    for (int it=0; it<8; it++){
        int idx = tid + it*256;
        int r = idx>>5, c = (idx&31)*4;
        float4 t = *(const float4*)(Qg + (long)r*Cn + c);
        float v[4] = {t.x,t.y,t.z,t.w};
        #pragma unroll
        for (int j=0;j<4;j++){
            uint32_t hh = cvt_tf32(v[j]);
            Qh[r*QS + c + j] = hh;
            Ql[r*QS + c + j] = cvt_tf32(v[j]-__uint_as_float(hh));
        }
    }
    if (tid < 64){ mrow[tid] = -1e30f; lrow[tid] = 0.f; }

    float accO[8][4];
    #pragma unroll
    for (int i=0;i<8;i++)
        #pragma unroll
        for (int j=0;j<4;j++) accO[i][j]=0.f;

    // register staging for K/V tiles
    float4 kreg[8], vreg[8];
    {
        #pragma unroll
        for (int it=0; it<8; it++){
            int idx = tid + it*256;
            int r = idx>>5, c = (idx&31)*4;
            kreg[it] = *(const float4*)(Kg + (long)r*Cn + c);
            vreg[it] = *(const float4*)(Vg + (long)r*Cn + c);
        }
    }

    for (int kt = 0; kt < Tn/64; kt++) {
        __syncthreads();   // prev PV / softmax reads done; Kt/Vs free
        // commit staged registers -> smem (convert + split)
        #pragma unroll
        for (int it=0; it<8; it++){
            int idx = tid + it*256;
            int r = idx>>5, c = (idx&31)*4;
            float v[4] = {kreg[it].x, kreg[it].y, kreg[it].z, kreg[it].w};
            #pragma unroll
            for (int j=0;j<4;j++){
                uint32_t hh = cvt_tf32(v[j]);
                Kh[r*QS + c + j] = hh;
                Kl[r*QS + c + j] = cvt_tf32(v[j]-__uint_as_float(hh));
            }
            uint4 uv;
            uv.x=cvt_tf32(vreg[it].x); uv.y=cvt_tf32(vreg[it].y);
            uv.z=cvt_tf32(vreg[it].z); uv.w=cvt_tf32(vreg[it].w);
            *(uint4*)(&Vt[r*VSd + c]) = uv;
        }
        __syncthreads();

        // prefetch next K/V tile into registers (latency hides behind compute)
        if (kt + 1 < Tn/64) {
            const float* Kgt = Kg + (long)(kt+1)*64*Cn;
            const float* Vgt = Vg + (long)(kt+1)*64*Cn;
            #pragma unroll
            for (int it=0; it<8; it++){
                int idx = tid + it*256;
                int r = idx>>5, c = (idx&31)*4;
                kreg[it] = *(const float4*)(Kgt + (long)r*Cn + c);
                vreg[it] = *(const float4*)(Vgt + (long)r*Cn + c);
            }
        }

        // S = Q K^T (3xTF32), warp tile 16x32
        float accS[4][4];
        #pragma unroll
        for (int i=0;i<4;i++)
            #pragma unroll
            for (int j=0;j<4;j++) accS[i][j]=0.f;

        #pragma unroll
        for (int ks=0; ks<128; ks+=8){
            int kk = ks + (lane&3);
            uint32_t bhf[4][2], blf[4][2];
            #pragma unroll
            for (int nt=0;nt<4;nt++){
                int c = wn*32 + nt*8 + (lane>>2);
                bhf[nt][0] = Kh[c*QS + kk];
                bhf[nt][1] = Kh[c*QS + kk + 4];
                blf[nt][0] = Kl[c*QS + kk];
                blf[nt][1] = Kl[c*QS + kk + 4];
            }
            int r = wm*16 + (lane>>2);
            uint32_t ah[4], al[4];
            ah[0]=Qh[r*QS+kk];     ah[1]=Qh[(r+8)*QS+kk];
            ah[2]=Qh[r*QS+kk+4];   ah[3]=Qh[(r+8)*QS+kk+4];
            al[0]=Ql[r*QS+kk];     al[1]=Ql[(r+8)*QS+kk];
            al[2]=Ql[r*QS+kk+4];   al[3]=Ql[(r+8)*QS+kk+4];
            #pragma unroll
            for (int nt=0;nt<4;nt++){
                mma8(accS[nt], ah, bhf[nt]);
                mma8(accS[nt], ah, blf[nt]);
                mma8(accS[nt], al, bhf[nt]);
            }
        }
        {
            int r = wm*16 + (lane>>2);
            #pragma unroll
            for (int nt=0;nt<4;nt++){
                int c = wn*32 + nt*8 + (lane&3)*2;
                Ssm[r*SSd + c]       = accS[nt][0]*SCALE;
                Ssm[r*SSd + c + 1]   = accS[nt][1]*SCALE;
                Ssm[(r+8)*SSd + c]   = accS[nt][2]*SCALE;
                Ssm[(r+8)*SSd + c+1] = accS[nt][3]*SCALE;
            }
        }
        __syncthreads();

        // softmax: 4 threads per row
        {
            int r = tid & 63, qd = tid >> 6;
            float* Sr = Ssm + r*SSd + qd*16;
            float mt_ = -1e30f;
            #pragma unroll
            for (int j=0;j<16;j++) mt_ = fmaxf(mt_, Sr[j]);
            pmax[qd*64 + r] = mt_;
            __syncthreads();
            float mold = mrow[r];
            float mnew = fmaxf(mold,
                         fmaxf(fmaxf(pmax[r], pmax[64+r]), fmaxf(pmax[128+r], pmax[192+r])));
            float s_ = 0.f;
            #pragma unroll
            for (int j=0;j<16;j++){
                float p = __expf(Sr[j] - mnew);
                Sr[j] = p; s_ += p;
            }
            psum[qd*64 + r] = s_;
            __syncthreads();
            if (qd == 0){
                float al_ = __expf(mold - mnew);
                lrow[r] = lrow[r]*al_ + psum[r] + psum[64+r] + psum[128+r] + psum[192+r];
                mrow[r] = mnew;
                arow[r] = al_;
            }
        }
        __syncthreads();

        // rescale + PV (1xTF32), warp tile 16x64
        {
            float a0 = arow[wm*16 + (lane>>2)];
            float a1 = arow[wm*16 + (lane>>2) + 8];
            #pragma unroll
            for (int nt=0;nt<8;nt++){
                accO[nt][0]*=a0; accO[nt][1]*=a0;
                accO[nt][2]*=a1; accO[nt][3]*=a1;
            }
            #pragma unroll
            for (int s0=0; s0<64; s0+=8){
                int kk = s0 + (lane&3);
                int r = wm*16 + (lane>>2);
                uint32_t ap[4];
                ap[0]=cvt_tf32(Ssm[r*SSd + kk]);
                ap[1]=cvt_tf32(Ssm[(r+8)*SSd + kk]);
                ap[2]=cvt_tf32(Ssm[r*SSd + kk + 4]);
                ap[3]=cvt_tf32(Ssm[(r+8)*SSd + kk + 4]);
                #pragma unroll
                for (int nt=0;nt<8;nt++){
                    int c = wn*64 + nt*8 + (lane>>2);
                    uint32_t bp[2] = { Vt[kk*VSd + c], Vt[(kk+4)*VSd + c] };
                    mma8(accO[nt], ap, bp);
                }
            }
        }
    }

    __syncthreads();
    // epilogue: x1 = x + O/l
    {
        int r = wm*16 + (lane>>2);
        float i0 = 1.f/lrow[r], i1 = 1.f/lrow[r+8];
        long row0 = (long)b*Tn + q0 + r;
        #pragma unroll
        for (int nt=0;nt<8;nt++){
            int c = h*Dn + wn*64 + nt*8 + (lane&3)*2;
            long o0 = row0*Cn + c, o1 = (row0+8)*Cn + c;
            float2 v0 = make_float2(accO[nt][0]*i0 + x[o0], accO[nt][1]*i0 + x[o0+1]);
            float2 v1 = make_float2(accO[nt][2]*i1 + x[o1], accO[nt][3]*i1 + x[o1+1]);
            *(float2*)(x1 + o0) = v0;
            *(float2*)(x1 + o1) = v1;
        }
    }
}

// ---------------- host launcher ----------------
extern "C" void kernel_launch(void* const* d_in, const int* in_sizes, int n_in,
                              void* d_out, int out_size)
{
    const float* x    = (const float*)d_in[0];
    const float* wq   = (const float*)d_in[1];
    const float* wk   = (const float*)d_in[2];
    const float* wv   = (const float*)d_in[3];
    const float* w1   = (const float*)d_in[4];
    const float* b1   = (const float*)d_in[5];
    const float* w2   = (const float*)d_in[6];
    const float* b2   = (const float*)d_in[7];
    const float* ln1g = (const float*)d_in[8];
    const float* ln1b = (const float*)d_in[9];
    const float* ln2g = (const float*)d_in[10];
    const float* ln2b = (const float*)d_in[11];
    float* out = (float*)d_out;

    float *h, *q, *k, *v, *x1, *h2, *ff;
    cudaGetSymbolAddress((void**)&h,  g_h);
    cudaGetSymbolAddress((void**)&q,  g_q);
    cudaGetSymbolAddress((void**)&k,  g_k);
    cudaGetSymbolAddress((void**)&v,  g_v);
    cudaGetSymbolAddress((void**)&x1, g_x1);
    cudaGetSymbolAddress((void**)&h2, g_h2);
    cudaGetSymbolAddress((void**)&ff, g_ff);

    // dynamic smem sizes: 2 buffers x tiles x 16x136 words x 4B
    const int SM1 = 2*2*16*136*4;   // 34816 B (SPLIT=1)
    const int SM3 = 2*4*16*136*4;   // 69632 B (SPLIT=3)

    cudaFuncSetAttribute(attn_mma, cudaFuncAttributeMaxDynamicSharedMemorySize,
                         ATTN_BYTES);
    cudaFuncSetAttribute(mma_gemm<1>, cudaFuncAttributeMaxDynamicSharedMemorySize, SM1);
    cudaFuncSetAttribute(mma_gemm<3>, cudaFuncAttributeMaxDynamicSharedMemorySize, SM3);

    // 1) LN1
    ln_kernel<<<Mrows, 256>>>(x, ln1g, ln1b, h);

    // 2) projections: q,k in 3xTF32 (score chain), v in 1xTF32
    dim3 pg(1, Mrows/128, Hn);
    mma_gemm<3><<<pg, 256, SM3>>>(h, wq, q, Mrows, Dn, Cn, Cn, Dn, Cn,
                             (long)Cn*Dn, (long)Dn, nullptr, 0, nullptr, 0);
    mma_gemm<3><<<pg, 256, SM3>>>(h, wk, k, Mrows, Dn, Cn, Cn, Dn, Cn,
                             (long)Cn*Dn, (long)Dn, nullptr, 0, nullptr, 0);
    mma_gemm<1><<<pg, 256, SM1>>>(h, wv, v, Mrows, Dn, Cn, Cn, Dn, Cn,
                             (long)Cn*Dn, (long)Dn, nullptr, 0, nullptr, 0);

    // 3) attention + residual
    attn_mma<<<dim3(Tn/64, Bsz*Hn), 256, ATTN_BYTES>>>(q, k, v, x, x1);

    // 4) LN2
    ln_kernel<<<Mrows, 256>>>(x1, ln2g, ln2b, h2);

    // 5) FF1: relu(h2 @ w1 + b1)
    mma_gemm<1><<<dim3(DffN/128, Mrows/128, 1), 256, SM1>>>(h2, w1, ff, Mrows, DffN, Cn,
                             Cn, DffN, DffN, 0L, 0L, b1, 1, nullptr, 0);

    // 6) FF2: out = x1 + (ff @ w2 + b2)
    mma_gemm<1><<<dim3(Cn/128, Mrows/128, 1), 256, SM1>>>(ff, w2, out, Mrows, Cn, DffN,
                             DffN, Cn, Cn, 0L, 0L, b2, 0, x1, Cn);
}